// round 2
// baseline (speedup 1.0000x reference)
#include <cuda_runtime.h>
#include <cuda_bf16.h>
#include <cstdint>

// ============================================================================
// TwoLayerChebNet: out = cheb(relu(cheb(x) @ W1^T + b1)) @ W2^T + b2
// cheb(x) = [T0 | T1 | T2] feature-major-interleaved, T0=x, T1=Lx, T2=2LT1-T0
// L given as COO (rows, cols, vals), E=3.2M, N=100000, F=H=256, O=64, K=3.
//
// Pipeline per launch (graph-capturable, allocation-free):
//   1) device-side CSR build: histogram -> single-block scan -> scatter
//   2) repack W1/W2 from (j, f*3+k) interleave to [k][j][f] contiguous
//   3) SpMM T1 = L x            (gather-only, 1 block/row, 256 thr = F)
//   4) SpMM T2 = 2 L T1 - x     (cheb combine fused in epilogue)
//   5) GEMM h = relu([T0 T1 T2] @ W1r^T + b1)   (SIMT fp32, 128x128x16)
//   6) SpMM h1 = L h            (h1 aliases T1 — T1 dead after step 5)
//   7) SpMM h2 = 2 L h1 - h     (h2 aliases T2)
//   8) GEMM out = [h h1 h2] @ W2r^T + b2        (128x64x16)
// ============================================================================

#define N_NODES 100000
#define FDIM    256
#define EDGES   3200000
#define HDIM    256
#define ODIM    64

// ---------------- scratch (device globals; no allocation allowed) -----------
__device__ float g_T1[(size_t)N_NODES * FDIM];   // also h1
__device__ float g_T2[(size_t)N_NODES * FDIM];   // also h2
__device__ float g_h [(size_t)N_NODES * FDIM];

__device__ int   g_rowptr[N_NODES + 1];
__device__ int   g_cursor[N_NODES];       // counts, then running fill cursor
__device__ int   g_ecol[EDGES];
__device__ float g_eval[EDGES];

__device__ float g_W1r[3 * HDIM * FDIM];  // [k][j][f]
__device__ float g_W2r[3 * ODIM * FDIM];  // [k][j][f]

// ---------------- CSR build --------------------------------------------------

__global__ void k_zero_counts() {
    int i = blockIdx.x * blockDim.x + threadIdx.x;
    if (i < N_NODES) g_cursor[i] = 0;
}

__global__ void k_hist(const int* __restrict__ rows) {
    int i = blockIdx.x * blockDim.x + threadIdx.x;
    if (i < EDGES) atomicAdd(&g_cursor[rows[i]], 1);
}

// Single-block exclusive scan over 100k counts (in g_cursor) -> g_rowptr,
// and reset g_cursor to the row start offsets (fill cursors).
__global__ void k_scan() {
    __shared__ int sums[1024];
    const int CH = (N_NODES + 1023) / 1024;  // 98 rows per thread
    const int t = threadIdx.x;
    const int base = t * CH;

    int s = 0;
    for (int i = 0; i < CH; i++) {
        int idx = base + i;
        if (idx < N_NODES) s += g_cursor[idx];
    }
    sums[t] = s;
    __syncthreads();

    // Hillis-Steele inclusive scan over 1024 partials
    for (int off = 1; off < 1024; off <<= 1) {
        int v = 0;
        if (t >= off) v = sums[t - off];
        __syncthreads();
        sums[t] += v;
        __syncthreads();
    }
    int run = (t == 0) ? 0 : sums[t - 1];

    for (int i = 0; i < CH; i++) {
        int idx = base + i;
        if (idx < N_NODES) {
            int c = g_cursor[idx];   // read count BEFORE overwrite
            g_rowptr[idx] = run;
            g_cursor[idx] = run;     // becomes the fill cursor
            run += c;
        }
    }
    if (t == 0) g_rowptr[N_NODES] = EDGES;
}

__global__ void k_scatter(const int* __restrict__ rows,
                          const int* __restrict__ cols,
                          const float* __restrict__ vals) {
    int i = blockIdx.x * blockDim.x + threadIdx.x;
    if (i >= EDGES) return;
    int r = rows[i];
    int p = atomicAdd(&g_cursor[r], 1);
    g_ecol[p] = cols[i];
    g_eval[p] = vals[i];
}

// ---------------- weight repack ---------------------------------------------
// Wr[k*Nout*256 + j*256 + f] = W[j*768 + f*3 + k]
__global__ void k_repack(const float* __restrict__ W, float* __restrict__ Wr, int Nout) {
    int i = blockIdx.x * blockDim.x + threadIdx.x;
    int total = 3 * Nout * FDIM;
    if (i >= total) return;
    int k = i / (Nout * FDIM);
    int r = i % (Nout * FDIM);
    int j = r / FDIM;
    int f = r % FDIM;
    Wr[i] = W[j * (FDIM * 3) + f * 3 + k];
}

// ---------------- SpMM: Y[row,:] = alpha * sum_e val*X[col,:]  (+ beta*Z) ----
// one 256-thread block per row; thread = feature column. Coalesced 1KB gathers.
__global__ __launch_bounds__(256) void k_spmm(const float* __restrict__ X,
                                              const float* __restrict__ Z,
                                              float* __restrict__ Y,
                                              float alpha, float beta) {
    const int row = blockIdx.x;
    const int f = threadIdx.x;
    const int s = g_rowptr[row];
    const int e = g_rowptr[row + 1];

    float acc0 = 0.f, acc1 = 0.f;
    int p = s;
    for (; p + 4 <= e; p += 4) {
        int c0 = g_ecol[p + 0], c1 = g_ecol[p + 1];
        int c2 = g_ecol[p + 2], c3 = g_ecol[p + 3];
        float v0 = g_eval[p + 0], v1 = g_eval[p + 1];
        float v2 = g_eval[p + 2], v3 = g_eval[p + 3];
        float x0 = X[(size_t)c0 * FDIM + f];
        float x1 = X[(size_t)c1 * FDIM + f];
        float x2 = X[(size_t)c2 * FDIM + f];
        float x3 = X[(size_t)c3 * FDIM + f];
        acc0 = fmaf(v0, x0, acc0);
        acc1 = fmaf(v1, x1, acc1);
        acc0 = fmaf(v2, x2, acc0);
        acc1 = fmaf(v3, x3, acc1);
    }
    for (; p < e; p++) {
        acc0 = fmaf(g_eval[p], X[(size_t)g_ecol[p] * FDIM + f], acc0);
    }
    float r = alpha * (acc0 + acc1);
    if (Z) r = fmaf(beta, Z[(size_t)row * FDIM + f], r);
    Y[(size_t)row * FDIM + f] = r;
}

// ---------------- GEMM: C[m,n] = sum_k sum_f A_k[m,f] * Wr[k][n,f] (+bias) ---
// BM=128, BK=16, TM=8; BN/TN templated (128/8 for layer1, 64/4 for layer2).
// 256 threads, 8x{8|4} micro-tile per thread, fp32 FFMA.
template <int BN, int TN, bool RELU>
__global__ __launch_bounds__(256) void k_gemm(const float* __restrict__ A0,
                                              const float* __restrict__ A1,
                                              const float* __restrict__ A2,
                                              const float* __restrict__ Wr,
                                              const float* __restrict__ bias,
                                              float* __restrict__ C,
                                              int M, int Nc) {
    constexpr int BM = 128, BK = 16, TM = 8;
    constexpr int TX = BN / TN;  // 16 in both configs

    __shared__ float As[BK][BM + 4];
    __shared__ float Bs[BK][BN + 4];

    const int tid = threadIdx.x;
    const int tx = tid % TX;
    const int ty = tid / TX;
    const int mtile = blockIdx.x * BM;
    const int ntile = blockIdx.y * BN;

    float acc[TM][TN];
#pragma unroll
    for (int i = 0; i < TM; i++)
#pragma unroll
        for (int j = 0; j < TN; j++) acc[i][j] = 0.f;

    const float* Aterm[3] = {A0, A1, A2};

    const int lr = tid >> 2;       // 0..63
    const int lq = tid & 3;        // 0..3  (k offset lq*4)

    for (int t = 0; t < 3; t++) {
        const float* __restrict__ A = Aterm[t];
        const float* __restrict__ B = Wr + (size_t)t * Nc * FDIM;

        for (int kk0 = 0; kk0 < FDIM; kk0 += BK) {
            // ---- load A tile [BM x BK], store k-major into As ----
#pragma unroll
            for (int rep = 0; rep < BM / 64; rep++) {
                int m = lr + rep * 64;
                int gm = mtile + m;
                float4 v = make_float4(0.f, 0.f, 0.f, 0.f);
                if (gm < M)
                    v = *(const float4*)(A + (size_t)gm * FDIM + kk0 + lq * 4);
                As[lq * 4 + 0][m] = v.x;
                As[lq * 4 + 1][m] = v.y;
                As[lq * 4 + 2][m] = v.z;
                As[lq * 4 + 3][m] = v.w;
            }
            // ---- load B tile [BN x BK] ----
#pragma unroll
            for (int rep = 0; rep < BN / 64; rep++) {
                int n = lr + rep * 64;
                float4 v = *(const float4*)(B + (size_t)(ntile + n) * FDIM + kk0 + lq * 4);
                Bs[lq * 4 + 0][n] = v.x;
                Bs[lq * 4 + 1][n] = v.y;
                Bs[lq * 4 + 2][n] = v.z;
                Bs[lq * 4 + 3][n] = v.w;
            }
            __syncthreads();

#pragma unroll
            for (int kk = 0; kk < BK; kk++) {
                float a[TM], b[TN];
                *(float4*)&a[0] = *(const float4*)&As[kk][ty * TM];
                *(float4*)&a[4] = *(const float4*)&As[kk][ty * TM + 4];
#pragma unroll
                for (int j = 0; j < TN; j += 4)
                    *(float4*)&b[j] = *(const float4*)&Bs[kk][tx * TN + j];
#pragma unroll
                for (int i = 0; i < TM; i++)
#pragma unroll
                    for (int j = 0; j < TN; j++)
                        acc[i][j] = fmaf(a[i], b[j], acc[i][j]);
            }
            __syncthreads();
        }
    }

    // ---- epilogue: bias (+relu), guarded store ----
#pragma unroll
    for (int i = 0; i < TM; i++) {
        int gm = mtile + ty * TM + i;
        if (gm >= M) continue;
#pragma unroll
        for (int j = 0; j < TN; j++) {
            int gn = ntile + tx * TN + j;
            float v = acc[i][j] + bias[gn];
            if (RELU) v = fmaxf(v, 0.f);
            C[(size_t)gm * Nc + gn] = v;
        }
    }
}

// ---------------- host orchestration ----------------------------------------

extern "C" void kernel_launch(void* const* d_in, const int* in_sizes, int n_in,
                              void* d_out, int out_size) {
    (void)n_in; (void)in_sizes; (void)out_size;
    const float* x    = (const float*)d_in[0];
    const int*   rows = (const int*)  d_in[1];
    const int*   cols = (const int*)  d_in[2];
    const float* vals = (const float*)d_in[3];
    const float* W1   = (const float*)d_in[4];
    const float* b1   = (const float*)d_in[5];
    const float* W2   = (const float*)d_in[6];
    const float* b2   = (const float*)d_in[7];
    float* out = (float*)d_out;

    float *T1, *T2, *h, *W1r, *W2r;
    cudaGetSymbolAddress((void**)&T1,  g_T1);
    cudaGetSymbolAddress((void**)&T2,  g_T2);
    cudaGetSymbolAddress((void**)&h,   g_h);
    cudaGetSymbolAddress((void**)&W1r, g_W1r);
    cudaGetSymbolAddress((void**)&W2r, g_W2r);

    const int M = N_NODES;

    // 1) CSR build
    k_zero_counts<<<(N_NODES + 255) / 256, 256>>>();
    k_hist<<<(EDGES + 255) / 256, 256>>>(rows);
    k_scan<<<1, 1024>>>();
    k_scatter<<<(EDGES + 255) / 256, 256>>>(rows, cols, vals);

    // 2) weight repack
    k_repack<<<(3 * HDIM * FDIM + 255) / 256, 256>>>(W1, W1r, HDIM);
    k_repack<<<(3 * ODIM * FDIM + 255) / 256, 256>>>(W2, W2r, ODIM);

    // 3-4) layer-1 Chebyshev terms
    k_spmm<<<N_NODES, 256>>>(x,  nullptr, T1, 1.f,  0.f);
    k_spmm<<<N_NODES, 256>>>(T1, x,       T2, 2.f, -1.f);

    // 5) h = relu([x T1 T2] @ W1r^T + b1)
    {
        dim3 grid((M + 127) / 128, HDIM / 128);
        k_gemm<128, 8, true><<<grid, 256>>>(x, T1, T2, W1r, b1, h, M, HDIM);
    }

    // 6-7) layer-2 Chebyshev terms (h1 aliases T1, h2 aliases T2 — safe:
    // layer-1 GEMM above is the last reader of T1/T2 and streams are ordered)
    k_spmm<<<N_NODES, 256>>>(h,  nullptr, T1, 1.f,  0.f);
    k_spmm<<<N_NODES, 256>>>(T1, h,       T2, 2.f, -1.f);

    // 8) out = [h h1 h2] @ W2r^T + b2
    {
        dim3 grid((M + 127) / 128, ODIM / 64);
        k_gemm<64, 4, false><<<grid, 256>>>(h, T1, T2, W2r, b2, out, M, ODIM);
    }
}

// round 5
// speedup vs baseline: 1.2188x; 1.2188x over previous
#include <cuda_runtime.h>
#include <cuda_bf16.h>
#include <cstdint>

// ============================================================================
// TwoLayerChebNet — mma.sync edition (sm_100 base target; no tcgen05).
//   SpMM: fp32 CSR gather, 1 block/row (round-2 proven).
//   GEMM: warp-level mma.sync.m16n8k16 bf16 with bf16x3 compensation:
//         C = Ah*Bh + Ah*Bl + Al*Bh, fp32 accumulate in registers.
//         A split to hi/lo ONCE per smem chunk; 3 passes run from smem.
// ============================================================================

#define N_NODES 100000
#define FDIM    256
#define EDGES   3200000
#define HDIM    256
#define ODIM    64
#define MTILES  ((N_NODES + 127) / 128)

// ---------------- scratch ----------------------------------------------------
__device__ float g_T1[(size_t)N_NODES * FDIM];   // also h1
__device__ float g_T2[(size_t)N_NODES * FDIM];   // also h2
__device__ float g_h [(size_t)N_NODES * FDIM];

__device__ int   g_rowptr[N_NODES + 1];
__device__ int   g_cursor[N_NODES];
__device__ int   g_ecol[EDGES];
__device__ float g_eval[EDGES];

__device__ __nv_bfloat16 g_W1h[3 * HDIM * FDIM];
__device__ __nv_bfloat16 g_W1l[3 * HDIM * FDIM];
__device__ __nv_bfloat16 g_W2h[3 * ODIM * FDIM];
__device__ __nv_bfloat16 g_W2l[3 * ODIM * FDIM];

// ---------------- helpers -----------------------------------------------------
__device__ __forceinline__ uint32_t smem_u32(const void* p) {
    uint32_t a;
    asm("{ .reg .u64 t; cvta.to.shared.u64 t, %1; cvt.u32.u64 %0, t; }" : "=r"(a) : "l"(p));
    return a;
}
__device__ __forceinline__ void split2(float a, float b, uint32_t& hi, uint32_t& lo) {
    __nv_bfloat16 ah = __float2bfloat16_rn(a), bh = __float2bfloat16_rn(b);
    __nv_bfloat16 al = __float2bfloat16_rn(a - __bfloat162float(ah));
    __nv_bfloat16 bl = __float2bfloat16_rn(b - __bfloat162float(bh));
    hi = (uint32_t)__bfloat16_as_ushort(ah) | ((uint32_t)__bfloat16_as_ushort(bh) << 16);
    lo = (uint32_t)__bfloat16_as_ushort(al) | ((uint32_t)__bfloat16_as_ushort(bl) << 16);
}
__device__ __forceinline__ void ldsm4(uint32_t& r0, uint32_t& r1, uint32_t& r2,
                                      uint32_t& r3, uint32_t addr) {
    asm volatile("ldmatrix.sync.aligned.m8n8.x4.shared.b16 {%0,%1,%2,%3}, [%4];"
                 : "=r"(r0), "=r"(r1), "=r"(r2), "=r"(r3) : "r"(addr));
}
__device__ __forceinline__ void mma16816(float* c, const uint32_t* a, const uint32_t* b) {
    asm volatile(
        "mma.sync.aligned.m16n8k16.row.col.f32.bf16.bf16.f32 "
        "{%0,%1,%2,%3}, {%4,%5,%6,%7}, {%8,%9}, {%0,%1,%2,%3};"
        : "+f"(c[0]), "+f"(c[1]), "+f"(c[2]), "+f"(c[3])
        : "r"(a[0]), "r"(a[1]), "r"(a[2]), "r"(a[3]), "r"(b[0]), "r"(b[1]));
}

// ---------------- CSR build (round-2 proven) ---------------------------------
__global__ void k_zero_counts() {
    int i = blockIdx.x * blockDim.x + threadIdx.x;
    if (i < N_NODES) g_cursor[i] = 0;
}
__global__ void k_hist(const int* __restrict__ rows) {
    int i = blockIdx.x * blockDim.x + threadIdx.x;
    if (i < EDGES) atomicAdd(&g_cursor[rows[i]], 1);
}
__global__ void k_scan() {
    __shared__ int sums[1024];
    const int CH = (N_NODES + 1023) / 1024;
    const int t = threadIdx.x;
    const int base = t * CH;
    int s = 0;
    for (int i = 0; i < CH; i++) {
        int idx = base + i;
        if (idx < N_NODES) s += g_cursor[idx];
    }
    sums[t] = s;
    __syncthreads();
    for (int off = 1; off < 1024; off <<= 1) {
        int v = 0;
        if (t >= off) v = sums[t - off];
        __syncthreads();
        sums[t] += v;
        __syncthreads();
    }
    int run = (t == 0) ? 0 : sums[t - 1];
    for (int i = 0; i < CH; i++) {
        int idx = base + i;
        if (idx < N_NODES) {
            int c = g_cursor[idx];
            g_rowptr[idx] = run;
            g_cursor[idx] = run;
            run += c;
        }
    }
    if (t == 0) g_rowptr[N_NODES] = EDGES;
}
__global__ void k_scatter(const int* __restrict__ rows,
                          const int* __restrict__ cols,
                          const float* __restrict__ vals) {
    int i = blockIdx.x * blockDim.x + threadIdx.x;
    if (i >= EDGES) return;
    int r = rows[i];
    int p = atomicAdd(&g_cursor[r], 1);
    g_ecol[p] = cols[i];
    g_eval[p] = vals[i];
}

// ---------------- weight repack: W[j][f*3+k] -> Wh/Wl [k][j][f] --------------
__global__ void k_repack(const float* __restrict__ W,
                         __nv_bfloat16* __restrict__ Wh,
                         __nv_bfloat16* __restrict__ Wl, int Nout) {
    int i = blockIdx.x * blockDim.x + threadIdx.x;
    int total = 3 * Nout * FDIM;
    if (i >= total) return;
    int k = i / (Nout * FDIM);
    int r = i % (Nout * FDIM);
    int j = r / FDIM;
    int f = r % FDIM;
    float v = W[j * (FDIM * 3) + f * 3 + k];
    __nv_bfloat16 h = __float2bfloat16_rn(v);
    Wh[i] = h;
    Wl[i] = __float2bfloat16_rn(v - __bfloat162float(h));
}

// ---------------- SpMM (round-2 proven, fp32) --------------------------------
__global__ __launch_bounds__(256) void k_spmm(const float* __restrict__ X,
                                              const float* __restrict__ Z,
                                              float* __restrict__ Y,
                                              float alpha, float beta) {
    const int row = blockIdx.x;
    const int f = threadIdx.x;
    const int s = g_rowptr[row];
    const int e = g_rowptr[row + 1];

    float acc0 = 0.f, acc1 = 0.f;
    int p = s;
    for (; p + 4 <= e; p += 4) {
        int c0 = g_ecol[p + 0], c1 = g_ecol[p + 1];
        int c2 = g_ecol[p + 2], c3 = g_ecol[p + 3];
        float v0 = g_eval[p + 0], v1 = g_eval[p + 1];
        float v2 = g_eval[p + 2], v3 = g_eval[p + 3];
        float x0 = X[(size_t)c0 * FDIM + f];
        float x1 = X[(size_t)c1 * FDIM + f];
        float x2 = X[(size_t)c2 * FDIM + f];
        float x3 = X[(size_t)c3 * FDIM + f];
        acc0 = fmaf(v0, x0, acc0);
        acc1 = fmaf(v1, x1, acc1);
        acc0 = fmaf(v2, x2, acc0);
        acc1 = fmaf(v3, x3, acc1);
    }
    for (; p < e; p++)
        acc0 = fmaf(g_eval[p], X[(size_t)g_ecol[p] * FDIM + f], acc0);

    float r = alpha * (acc0 + acc1);
    if (Z) r = fmaf(beta, Z[(size_t)row * FDIM + f], r);
    Y[(size_t)row * FDIM + f] = r;
}

// ---------------- mma.sync GEMM ----------------------------------------------
// C[M x Nc] = [A0|A1|A2](fp32, M x 768) @ W^T (hi/lo bf16, Nc x 768), + bias.
// CTA tile: 128 x BN. 8 warps, each WM x WN. BK = 32 per chunk.
// smem row stride 40 bf16 (80B) — conflict-free for ldmatrix.
template <int BN, int WM, int WN, bool RELU>
__global__ __launch_bounds__(256) void k_mma(
    const float* __restrict__ A0, const float* __restrict__ A1,
    const float* __restrict__ A2,
    const __nv_bfloat16* __restrict__ Wh, const __nv_bfloat16* __restrict__ Wl,
    const float* __restrict__ bias, float* __restrict__ C, int M, int Nc)
{
    constexpr int MT = WM / 16;          // m16 tiles per warp
    constexpr int NT = WN / 8;           // n8 tiles per warp
    constexpr int WARPS_N = BN / WN;
    constexpr int STR = 40;              // smem row stride in bf16
    constexpr int TPR = 256 / BN;        // threads per B row (2 or 4)

    __shared__ __align__(16) uint16_t sAh[128 * STR];
    __shared__ __align__(16) uint16_t sAl[128 * STR];
    __shared__ __align__(16) uint16_t sBh[BN * STR];
    __shared__ __align__(16) uint16_t sBl[BN * STR];

    const int tid = threadIdx.x;
    const int wid = tid >> 5;
    const int lane = tid & 31;
    const int warp_m = wid / WARPS_N;
    const int warp_n = wid % WARPS_N;
    const int mtile = blockIdx.x * 128;
    const int ntile = blockIdx.y * BN;

    const uint32_t sAh_b = smem_u32(sAh), sAl_b = smem_u32(sAl);
    const uint32_t sBh_b = smem_u32(sBh), sBl_b = smem_u32(sBl);

    float acc[MT][NT][4];
#pragma unroll
    for (int i = 0; i < MT; i++)
#pragma unroll
        for (int j = 0; j < NT; j++)
#pragma unroll
            for (int r = 0; r < 4; r++) acc[i][j][r] = 0.f;

    const float* Aterm[3] = {A0, A1, A2};

    // loader indices
    const int a_row = tid >> 1, a_seg = tid & 1;            // A: 2 thr/row, 16 f each
    const int b_row = tid / TPR, b_seg = tid % TPR;         // B: TPR thr/row

    // ldmatrix per-lane addresses (element offsets within tile)
    const int a_r = lane & 15, a_c = (lane >> 4) << 3;                    // A/x4
    const int b_r = ((lane >> 4) << 3) + (lane & 7), b_c = ((lane >> 3) & 1) << 3;

    for (int t = 0; t < 3; t++) {
        const float* __restrict__ A = Aterm[t];
        const __nv_bfloat16* __restrict__ BhT = Wh + (size_t)t * Nc * FDIM;
        const __nv_bfloat16* __restrict__ BlT = Wl + (size_t)t * Nc * FDIM;

        for (int kc = 0; kc < FDIM; kc += 32) {
            // ---- A chunk: 128 rows x 32 fp32 -> hi/lo bf16 smem tiles ----
            {
                int gm = mtile + a_row;
                uint32_t hi[8], lo[8];
                if (gm < M) {
                    const float4* src =
                        (const float4*)(A + (size_t)gm * FDIM + kc + a_seg * 16);
#pragma unroll
                    for (int w = 0; w < 4; w++) {
                        float4 v = src[w];
                        split2(v.x, v.y, hi[w * 2 + 0], lo[w * 2 + 0]);
                        split2(v.z, v.w, hi[w * 2 + 1], lo[w * 2 + 1]);
                    }
                } else {
#pragma unroll
                    for (int r = 0; r < 8; r++) { hi[r] = 0; lo[r] = 0; }
                }
                uint4* dh = (uint4*)&sAh[a_row * STR + a_seg * 16];
                uint4* dl = (uint4*)&sAl[a_row * STR + a_seg * 16];
                dh[0] = make_uint4(hi[0], hi[1], hi[2], hi[3]);
                dh[1] = make_uint4(hi[4], hi[5], hi[6], hi[7]);
                dl[0] = make_uint4(lo[0], lo[1], lo[2], lo[3]);
                dl[1] = make_uint4(lo[4], lo[5], lo[6], lo[7]);
            }
            // ---- B chunk: BN rows x 32 bf16 (hi and lo) ----
            {
                const size_t off = (size_t)(ntile + b_row) * FDIM + kc + b_seg * (32 / TPR);
                const uint4* sh = (const uint4*)(BhT + off);
                const uint4* sl = (const uint4*)(BlT + off);
                uint4* dh = (uint4*)&sBh[b_row * STR + b_seg * (32 / TPR)];
                uint4* dl = (uint4*)&sBl[b_row * STR + b_seg * (32 / TPR)];
#pragma unroll
                for (int u = 0; u < 4 / TPR; u++) { dh[u] = sh[u]; dl[u] = sl[u]; }
            }
            __syncthreads();

            // ---- compute: 2 k16 steps, 3 compensation passes from smem ----
#pragma unroll
            for (int ks = 0; ks < 2; ks++) {
                uint32_t ah[MT][4], al[MT][4], bh[NT][2], bl[NT][2];
#pragma unroll
                for (int i = 0; i < MT; i++) {
                    uint32_t eoff =
                        (uint32_t)((warp_m * WM + i * 16 + a_r) * STR + ks * 16 + a_c) * 2;
                    ldsm4(ah[i][0], ah[i][1], ah[i][2], ah[i][3], sAh_b + eoff);
                    ldsm4(al[i][0], al[i][1], al[i][2], al[i][3], sAl_b + eoff);
                }
#pragma unroll
                for (int jj = 0; jj < NT / 2; jj++) {
                    uint32_t eoff =
                        (uint32_t)((warp_n * WN + jj * 16 + b_r) * STR + ks * 16 + b_c) * 2;
                    ldsm4(bh[2 * jj][0], bh[2 * jj][1], bh[2 * jj + 1][0],
                          bh[2 * jj + 1][1], sBh_b + eoff);
                    ldsm4(bl[2 * jj][0], bl[2 * jj][1], bl[2 * jj + 1][0],
                          bl[2 * jj + 1][1], sBl_b + eoff);
                }
#pragma unroll
                for (int i = 0; i < MT; i++)
#pragma unroll
                    for (int j = 0; j < NT; j++) {
                        mma16816(acc[i][j], ah[i], bh[j]);
                        mma16816(acc[i][j], ah[i], bl[j]);
                        mma16816(acc[i][j], al[i], bh[j]);
                    }
            }
            __syncthreads();
        }
    }

    // ---- epilogue ----
#pragma unroll
    for (int i = 0; i < MT; i++) {
        int gm0 = mtile + warp_m * WM + i * 16 + (lane >> 2);
#pragma unroll
        for (int j = 0; j < NT; j++) {
            int gn = ntile + warp_n * WN + j * 8 + (lane & 3) * 2;
            float bv0 = bias[gn], bv1 = bias[gn + 1];
            float v0 = acc[i][j][0] + bv0, v1 = acc[i][j][1] + bv1;
            float v2 = acc[i][j][2] + bv0, v3 = acc[i][j][3] + bv1;
            if (RELU) {
                v0 = fmaxf(v0, 0.f); v1 = fmaxf(v1, 0.f);
                v2 = fmaxf(v2, 0.f); v3 = fmaxf(v3, 0.f);
            }
            if (gm0 < M) {
                C[(size_t)gm0 * Nc + gn]     = v0;
                C[(size_t)gm0 * Nc + gn + 1] = v1;
            }
            if (gm0 + 8 < M) {
                C[(size_t)(gm0 + 8) * Nc + gn]     = v2;
                C[(size_t)(gm0 + 8) * Nc + gn + 1] = v3;
            }
        }
    }
}

// ---------------- host orchestration ----------------------------------------
extern "C" void kernel_launch(void* const* d_in, const int* in_sizes, int n_in,
                              void* d_out, int out_size) {
    (void)n_in; (void)in_sizes; (void)out_size;
    const float* x    = (const float*)d_in[0];
    const int*   rows = (const int*)  d_in[1];
    const int*   cols = (const int*)  d_in[2];
    const float* vals = (const float*)d_in[3];
    const float* W1   = (const float*)d_in[4];
    const float* b1   = (const float*)d_in[5];
    const float* W2   = (const float*)d_in[6];
    const float* b2   = (const float*)d_in[7];
    float* out = (float*)d_out;

    float *T1, *T2, *h;
    __nv_bfloat16 *W1h, *W1l, *W2h, *W2l;
    cudaGetSymbolAddress((void**)&T1, g_T1);
    cudaGetSymbolAddress((void**)&T2, g_T2);
    cudaGetSymbolAddress((void**)&h,  g_h);
    cudaGetSymbolAddress((void**)&W1h, g_W1h);
    cudaGetSymbolAddress((void**)&W1l, g_W1l);
    cudaGetSymbolAddress((void**)&W2h, g_W2h);
    cudaGetSymbolAddress((void**)&W2l, g_W2l);

    const int M = N_NODES;

    // 1) CSR build
    k_zero_counts<<<(N_NODES + 255) / 256, 256>>>();
    k_hist<<<(EDGES + 255) / 256, 256>>>(rows);
    k_scan<<<1, 1024>>>();
    k_scatter<<<(EDGES + 255) / 256, 256>>>(rows, cols, vals);

    // 2) weight repack (hi/lo split)
    k_repack<<<(3 * HDIM * FDIM + 255) / 256, 256>>>(W1, W1h, W1l, HDIM);
    k_repack<<<(3 * ODIM * FDIM + 255) / 256, 256>>>(W2, W2h, W2l, ODIM);

    // 3) layer-1 Chebyshev
    k_spmm<<<N_NODES, 256>>>(x,  nullptr, T1, 1.f,  0.f);
    k_spmm<<<N_NODES, 256>>>(T1, x,       T2, 2.f, -1.f);

    // 4) h = relu([x T1 T2] @ W1^T + b1)
    {
        dim3 grid(MTILES, HDIM / 128);
        k_mma<128, 64, 32, true><<<grid, 256>>>(x, T1, T2, W1h, W1l, b1, h, M, HDIM);
    }

    // 5) layer-2 Chebyshev (aliases T1/T2; GEMM above was last reader)
    k_spmm<<<N_NODES, 256>>>(h,  nullptr, T1, 1.f,  0.f);
    k_spmm<<<N_NODES, 256>>>(T1, h,       T2, 2.f, -1.f);

    // 6) out = [h h1 h2] @ W2^T + b2
    {
        dim3 grid(MTILES, 1);
        k_mma<64, 32, 32, false><<<grid, 256>>>(h, T1, T2, W2h, W2l, b2, out, M, ODIM);
    }
}

// round 6
// speedup vs baseline: 1.2192x; 1.0003x over previous
#include <cuda_runtime.h>
#include <cuda_bf16.h>
#include <cstdint>

// ============================================================================
// TwoLayerChebNet — mma.sync edition (sm_100 base target; no tcgen05).
//   SpMM: fp32 CSR gather, 1 block/row (round-2 proven).
//   GEMM: warp-level mma.sync.m16n8k16 bf16 with bf16x3 compensation:
//         C = Ah*Bh + Ah*Bl + Al*Bh, fp32 accumulate in registers.
//         A split to hi/lo ONCE per smem chunk; 3 passes run from smem.
// ============================================================================

#define N_NODES 100000
#define FDIM    256
#define EDGES   3200000
#define HDIM    256
#define ODIM    64
#define MTILES  ((N_NODES + 127) / 128)

// ---------------- scratch ----------------------------------------------------
__device__ float g_T1[(size_t)N_NODES * FDIM];   // also h1
__device__ float g_T2[(size_t)N_NODES * FDIM];   // also h2
__device__ float g_h [(size_t)N_NODES * FDIM];

__device__ int   g_rowptr[N_NODES + 1];
__device__ int   g_cursor[N_NODES];
__device__ int   g_ecol[EDGES];
__device__ float g_eval[EDGES];

__device__ __nv_bfloat16 g_W1h[3 * HDIM * FDIM];
__device__ __nv_bfloat16 g_W1l[3 * HDIM * FDIM];
__device__ __nv_bfloat16 g_W2h[3 * ODIM * FDIM];
__device__ __nv_bfloat16 g_W2l[3 * ODIM * FDIM];

// ---------------- helpers -----------------------------------------------------
__device__ __forceinline__ uint32_t smem_u32(const void* p) {
    uint32_t a;
    asm("{ .reg .u64 t; cvta.to.shared.u64 t, %1; cvt.u32.u64 %0, t; }" : "=r"(a) : "l"(p));
    return a;
}
__device__ __forceinline__ void split2(float a, float b, uint32_t& hi, uint32_t& lo) {
    __nv_bfloat16 ah = __float2bfloat16_rn(a), bh = __float2bfloat16_rn(b);
    __nv_bfloat16 al = __float2bfloat16_rn(a - __bfloat162float(ah));
    __nv_bfloat16 bl = __float2bfloat16_rn(b - __bfloat162float(bh));
    hi = (uint32_t)__bfloat16_as_ushort(ah) | ((uint32_t)__bfloat16_as_ushort(bh) << 16);
    lo = (uint32_t)__bfloat16_as_ushort(al) | ((uint32_t)__bfloat16_as_ushort(bl) << 16);
}
__device__ __forceinline__ void ldsm4(uint32_t& r0, uint32_t& r1, uint32_t& r2,
                                      uint32_t& r3, uint32_t addr) {
    asm volatile("ldmatrix.sync.aligned.m8n8.x4.shared.b16 {%0,%1,%2,%3}, [%4];"
                 : "=r"(r0), "=r"(r1), "=r"(r2), "=r"(r3) : "r"(addr));
}
__device__ __forceinline__ void mma16816(float* c, const uint32_t* a, const uint32_t* b) {
    asm volatile(
        "mma.sync.aligned.m16n8k16.row.col.f32.bf16.bf16.f32 "
        "{%0,%1,%2,%3}, {%4,%5,%6,%7}, {%8,%9}, {%0,%1,%2,%3};"
        : "+f"(c[0]), "+f"(c[1]), "+f"(c[2]), "+f"(c[3])
        : "r"(a[0]), "r"(a[1]), "r"(a[2]), "r"(a[3]), "r"(b[0]), "r"(b[1]));
}

// ---------------- CSR build (round-2 proven) ---------------------------------
__global__ void k_zero_counts() {
    int i = blockIdx.x * blockDim.x + threadIdx.x;
    if (i < N_NODES) g_cursor[i] = 0;
}
__global__ void k_hist(const int* __restrict__ rows) {
    int i = blockIdx.x * blockDim.x + threadIdx.x;
    if (i < EDGES) atomicAdd(&g_cursor[rows[i]], 1);
}
__global__ void k_scan() {
    __shared__ int sums[1024];
    const int CH = (N_NODES + 1023) / 1024;
    const int t = threadIdx.x;
    const int base = t * CH;
    int s = 0;
    for (int i = 0; i < CH; i++) {
        int idx = base + i;
        if (idx < N_NODES) s += g_cursor[idx];
    }
    sums[t] = s;
    __syncthreads();
    for (int off = 1; off < 1024; off <<= 1) {
        int v = 0;
        if (t >= off) v = sums[t - off];
        __syncthreads();
        sums[t] += v;
        __syncthreads();
    }
    int run = (t == 0) ? 0 : sums[t - 1];
    for (int i = 0; i < CH; i++) {
        int idx = base + i;
        if (idx < N_NODES) {
            int c = g_cursor[idx];
            g_rowptr[idx] = run;
            g_cursor[idx] = run;
            run += c;
        }
    }
    if (t == 0) g_rowptr[N_NODES] = EDGES;
}
__global__ void k_scatter(const int* __restrict__ rows,
                          const int* __restrict__ cols,
                          const float* __restrict__ vals) {
    int i = blockIdx.x * blockDim.x + threadIdx.x;
    if (i >= EDGES) return;
    int r = rows[i];
    int p = atomicAdd(&g_cursor[r], 1);
    g_ecol[p] = cols[i];
    g_eval[p] = vals[i];
}

// ---------------- weight repack: W[j][f*3+k] -> Wh/Wl [k][j][f] --------------
__global__ void k_repack(const float* __restrict__ W,
                         __nv_bfloat16* __restrict__ Wh,
                         __nv_bfloat16* __restrict__ Wl, int Nout) {
    int i = blockIdx.x * blockDim.x + threadIdx.x;
    int total = 3 * Nout * FDIM;
    if (i >= total) return;
    int k = i / (Nout * FDIM);
    int r = i % (Nout * FDIM);
    int j = r / FDIM;
    int f = r % FDIM;
    float v = W[j * (FDIM * 3) + f * 3 + k];
    __nv_bfloat16 h = __float2bfloat16_rn(v);
    Wh[i] = h;
    Wl[i] = __float2bfloat16_rn(v - __bfloat162float(h));
}

// ---------------- SpMM (round-2 proven, fp32) --------------------------------
__global__ __launch_bounds__(256) void k_spmm(const float* __restrict__ X,
                                              const float* __restrict__ Z,
                                              float* __restrict__ Y,
                                              float alpha, float beta) {
    const int row = blockIdx.x;
    const int f = threadIdx.x;
    const int s = g_rowptr[row];
    const int e = g_rowptr[row + 1];

    float acc0 = 0.f, acc1 = 0.f;
    int p = s;
    for (; p + 4 <= e; p += 4) {
        int c0 = g_ecol[p + 0], c1 = g_ecol[p + 1];
        int c2 = g_ecol[p + 2], c3 = g_ecol[p + 3];
        float v0 = g_eval[p + 0], v1 = g_eval[p + 1];
        float v2 = g_eval[p + 2], v3 = g_eval[p + 3];
        float x0 = X[(size_t)c0 * FDIM + f];
        float x1 = X[(size_t)c1 * FDIM + f];
        float x2 = X[(size_t)c2 * FDIM + f];
        float x3 = X[(size_t)c3 * FDIM + f];
        acc0 = fmaf(v0, x0, acc0);
        acc1 = fmaf(v1, x1, acc1);
        acc0 = fmaf(v2, x2, acc0);
        acc1 = fmaf(v3, x3, acc1);
    }
    for (; p < e; p++)
        acc0 = fmaf(g_eval[p], X[(size_t)g_ecol[p] * FDIM + f], acc0);

    float r = alpha * (acc0 + acc1);
    if (Z) r = fmaf(beta, Z[(size_t)row * FDIM + f], r);
    Y[(size_t)row * FDIM + f] = r;
}

// ---------------- mma.sync GEMM ----------------------------------------------
// C[M x Nc] = [A0|A1|A2](fp32, M x 768) @ W^T (hi/lo bf16, Nc x 768), + bias.
// CTA tile: 128 x BN. 8 warps, each WM x WN. BK = 32 per chunk.
// smem row stride 40 bf16 (80B) — conflict-free for ldmatrix.
template <int BN, int WM, int WN, bool RELU>
__global__ __launch_bounds__(256) void k_mma(
    const float* __restrict__ A0, const float* __restrict__ A1,
    const float* __restrict__ A2,
    const __nv_bfloat16* __restrict__ Wh, const __nv_bfloat16* __restrict__ Wl,
    const float* __restrict__ bias, float* __restrict__ C, int M, int Nc)
{
    constexpr int MT = WM / 16;          // m16 tiles per warp
    constexpr int NT = WN / 8;           // n8 tiles per warp
    constexpr int WARPS_N = BN / WN;
    constexpr int STR = 40;              // smem row stride in bf16
    constexpr int TPR = 256 / BN;        // threads per B row (2 or 4)

    __shared__ __align__(16) uint16_t sAh[128 * STR];
    __shared__ __align__(16) uint16_t sAl[128 * STR];
    __shared__ __align__(16) uint16_t sBh[BN * STR];
    __shared__ __align__(16) uint16_t sBl[BN * STR];

    const int tid = threadIdx.x;
    const int wid = tid >> 5;
    const int lane = tid & 31;
    const int warp_m = wid / WARPS_N;
    const int warp_n = wid % WARPS_N;
    const int mtile = blockIdx.x * 128;
    const int ntile = blockIdx.y * BN;

    const uint32_t sAh_b = smem_u32(sAh), sAl_b = smem_u32(sAl);
    const uint32_t sBh_b = smem_u32(sBh), sBl_b = smem_u32(sBl);

    float acc[MT][NT][4];
#pragma unroll
    for (int i = 0; i < MT; i++)
#pragma unroll
        for (int j = 0; j < NT; j++)
#pragma unroll
            for (int r = 0; r < 4; r++) acc[i][j][r] = 0.f;

    const float* Aterm[3] = {A0, A1, A2};

    // loader indices
    const int a_row = tid >> 1, a_seg = tid & 1;            // A: 2 thr/row, 16 f each
    const int b_row = tid / TPR, b_seg = tid % TPR;         // B: TPR thr/row

    // ldmatrix per-lane addresses (element offsets within tile)
    const int a_r = lane & 15, a_c = (lane >> 4) << 3;                    // A/x4
    const int b_r = ((lane >> 4) << 3) + (lane & 7), b_c = ((lane >> 3) & 1) << 3;

    for (int t = 0; t < 3; t++) {
        const float* __restrict__ A = Aterm[t];
        const __nv_bfloat16* __restrict__ BhT = Wh + (size_t)t * Nc * FDIM;
        const __nv_bfloat16* __restrict__ BlT = Wl + (size_t)t * Nc * FDIM;

        for (int kc = 0; kc < FDIM; kc += 32) {
            // ---- A chunk: 128 rows x 32 fp32 -> hi/lo bf16 smem tiles ----
            {
                int gm = mtile + a_row;
                uint32_t hi[8], lo[8];
                if (gm < M) {
                    const float4* src =
                        (const float4*)(A + (size_t)gm * FDIM + kc + a_seg * 16);
#pragma unroll
                    for (int w = 0; w < 4; w++) {
                        float4 v = src[w];
                        split2(v.x, v.y, hi[w * 2 + 0], lo[w * 2 + 0]);
                        split2(v.z, v.w, hi[w * 2 + 1], lo[w * 2 + 1]);
                    }
                } else {
#pragma unroll
                    for (int r = 0; r < 8; r++) { hi[r] = 0; lo[r] = 0; }
                }
                uint4* dh = (uint4*)&sAh[a_row * STR + a_seg * 16];
                uint4* dl = (uint4*)&sAl[a_row * STR + a_seg * 16];
                dh[0] = make_uint4(hi[0], hi[1], hi[2], hi[3]);
                dh[1] = make_uint4(hi[4], hi[5], hi[6], hi[7]);
                dl[0] = make_uint4(lo[0], lo[1], lo[2], lo[3]);
                dl[1] = make_uint4(lo[4], lo[5], lo[6], lo[7]);
            }
            // ---- B chunk: BN rows x 32 bf16 (hi and lo) ----
            {
                const size_t off = (size_t)(ntile + b_row) * FDIM + kc + b_seg * (32 / TPR);
                const uint4* sh = (const uint4*)(BhT + off);
                const uint4* sl = (const uint4*)(BlT + off);
                uint4* dh = (uint4*)&sBh[b_row * STR + b_seg * (32 / TPR)];
                uint4* dl = (uint4*)&sBl[b_row * STR + b_seg * (32 / TPR)];
#pragma unroll
                for (int u = 0; u < 4 / TPR; u++) { dh[u] = sh[u]; dl[u] = sl[u]; }
            }
            __syncthreads();

            // ---- compute: 2 k16 steps, 3 compensation passes from smem ----
#pragma unroll
            for (int ks = 0; ks < 2; ks++) {
                uint32_t ah[MT][4], al[MT][4], bh[NT][2], bl[NT][2];
#pragma unroll
                for (int i = 0; i < MT; i++) {
                    uint32_t eoff =
                        (uint32_t)((warp_m * WM + i * 16 + a_r) * STR + ks * 16 + a_c) * 2;
                    ldsm4(ah[i][0], ah[i][1], ah[i][2], ah[i][3], sAh_b + eoff);
                    ldsm4(al[i][0], al[i][1], al[i][2], al[i][3], sAl_b + eoff);
                }
#pragma unroll
                for (int jj = 0; jj < NT / 2; jj++) {
                    uint32_t eoff =
                        (uint32_t)((warp_n * WN + jj * 16 + b_r) * STR + ks * 16 + b_c) * 2;
                    ldsm4(bh[2 * jj][0], bh[2 * jj][1], bh[2 * jj + 1][0],
                          bh[2 * jj + 1][1], sBh_b + eoff);
                    ldsm4(bl[2 * jj][0], bl[2 * jj][1], bl[2 * jj + 1][0],
                          bl[2 * jj + 1][1], sBl_b + eoff);
                }
#pragma unroll
                for (int i = 0; i < MT; i++)
#pragma unroll
                    for (int j = 0; j < NT; j++) {
                        mma16816(acc[i][j], ah[i], bh[j]);
                        mma16816(acc[i][j], ah[i], bl[j]);
                        mma16816(acc[i][j], al[i], bh[j]);
                    }
            }
            __syncthreads();
        }
    }

    // ---- epilogue ----
#pragma unroll
    for (int i = 0; i < MT; i++) {
        int gm0 = mtile + warp_m * WM + i * 16 + (lane >> 2);
#pragma unroll
        for (int j = 0; j < NT; j++) {
            int gn = ntile + warp_n * WN + j * 8 + (lane & 3) * 2;
            float bv0 = bias[gn], bv1 = bias[gn + 1];
            float v0 = acc[i][j][0] + bv0, v1 = acc[i][j][1] + bv1;
            float v2 = acc[i][j][2] + bv0, v3 = acc[i][j][3] + bv1;
            if (RELU) {
                v0 = fmaxf(v0, 0.f); v1 = fmaxf(v1, 0.f);
                v2 = fmaxf(v2, 0.f); v3 = fmaxf(v3, 0.f);
            }
            if (gm0 < M) {
                C[(size_t)gm0 * Nc + gn]     = v0;
                C[(size_t)gm0 * Nc + gn + 1] = v1;
            }
            if (gm0 + 8 < M) {
                C[(size_t)(gm0 + 8) * Nc + gn]     = v2;
                C[(size_t)(gm0 + 8) * Nc + gn + 1] = v3;
            }
        }
    }
}

// ---------------- host orchestration ----------------------------------------
extern "C" void kernel_launch(void* const* d_in, const int* in_sizes, int n_in,
                              void* d_out, int out_size) {
    (void)n_in; (void)in_sizes; (void)out_size;
    const float* x    = (const float*)d_in[0];
    const int*   rows = (const int*)  d_in[1];
    const int*   cols = (const int*)  d_in[2];
    const float* vals = (const float*)d_in[3];
    const float* W1   = (const float*)d_in[4];
    const float* b1   = (const float*)d_in[5];
    const float* W2   = (const float*)d_in[6];
    const float* b2   = (const float*)d_in[7];
    float* out = (float*)d_out;

    float *T1, *T2, *h;
    __nv_bfloat16 *W1h, *W1l, *W2h, *W2l;
    cudaGetSymbolAddress((void**)&T1, g_T1);
    cudaGetSymbolAddress((void**)&T2, g_T2);
    cudaGetSymbolAddress((void**)&h,  g_h);
    cudaGetSymbolAddress((void**)&W1h, g_W1h);
    cudaGetSymbolAddress((void**)&W1l, g_W1l);
    cudaGetSymbolAddress((void**)&W2h, g_W2h);
    cudaGetSymbolAddress((void**)&W2l, g_W2l);

    const int M = N_NODES;

    // 1) CSR build
    k_zero_counts<<<(N_NODES + 255) / 256, 256>>>();
    k_hist<<<(EDGES + 255) / 256, 256>>>(rows);
    k_scan<<<1, 1024>>>();
    k_scatter<<<(EDGES + 255) / 256, 256>>>(rows, cols, vals);

    // 2) weight repack (hi/lo split)
    k_repack<<<(3 * HDIM * FDIM + 255) / 256, 256>>>(W1, W1h, W1l, HDIM);
    k_repack<<<(3 * ODIM * FDIM + 255) / 256, 256>>>(W2, W2h, W2l, ODIM);

    // 3) layer-1 Chebyshev
    k_spmm<<<N_NODES, 256>>>(x,  nullptr, T1, 1.f,  0.f);
    k_spmm<<<N_NODES, 256>>>(T1, x,       T2, 2.f, -1.f);

    // 4) h = relu([x T1 T2] @ W1^T + b1)
    {
        dim3 grid(MTILES, HDIM / 128);
        k_mma<128, 64, 32, true><<<grid, 256>>>(x, T1, T2, W1h, W1l, b1, h, M, HDIM);
    }

    // 5) layer-2 Chebyshev (aliases T1/T2; GEMM above was last reader)
    k_spmm<<<N_NODES, 256>>>(h,  nullptr, T1, 1.f,  0.f);
    k_spmm<<<N_NODES, 256>>>(T1, h,       T2, 2.f, -1.f);

    // 6) out = [h h1 h2] @ W2^T + b2
    {
        dim3 grid(MTILES, 1);
        k_mma<64, 32, 32, false><<<grid, 256>>>(h, T1, T2, W2h, W2l, b2, out, M, ODIM);
    }
}